// round 13
// baseline (speedup 1.0000x reference)
#include <cuda_runtime.h>
#include <cuda_fp16.h>
#include <cstdint>
#include <math.h>

#define BB 2
#define SS 2048
#define DD 1024
#define HH 16
#define DKK 64

#define GM 4096
#define GN 1024
#define GK 1024
#define PITCH 144   // gemm smem row pitch: 64 fp16 + 8 pad

// ---------------------------------------------------------------------------
// Scratch
// ---------------------------------------------------------------------------
__device__ float g_cos[SS*32];
__device__ float g_sin[SS*32];
__device__ __half g_wh[4*DD*DD];   // fp16 weights [N,K]: Wq,Wk,Wv,Wo
__device__ __half g_ah[3*GM*GK];   // fp16 activations; slot0 reused for attn out
__device__ __half g_qh2[BB*SS*DD]; // [B,H,S,DK] (pre-scaled by 0.125)
__device__ __half g_kh2[BB*SS*DD];
__device__ __half g_vh2[BB*SS*DD];

// ---------------------------------------------------------------------------
// helpers
// ---------------------------------------------------------------------------
__device__ __forceinline__ uint32_t smem_u32(const void* p) {
    uint32_t a;
    asm("{ .reg .u64 t; cvta.to.shared.u64 t, %1; cvt.u32.u64 %0, t; }"
        : "=r"(a) : "l"(p));
    return a;
}
__device__ __forceinline__ void ldsm_x4(uint32_t* r, uint32_t addr) {
    asm volatile("ldmatrix.sync.aligned.m8n8.x4.shared.b16 {%0,%1,%2,%3}, [%4];"
        : "=r"(r[0]), "=r"(r[1]), "=r"(r[2]), "=r"(r[3]) : "r"(addr));
}
__device__ __forceinline__ void ldsm_x4_t(uint32_t* r, uint32_t addr) {
    asm volatile("ldmatrix.sync.aligned.m8n8.x4.trans.shared.b16 {%0,%1,%2,%3}, [%4];"
        : "=r"(r[0]), "=r"(r[1]), "=r"(r[2]), "=r"(r[3]) : "r"(addr));
}
__device__ __forceinline__ void mma_f16(float* d, const uint32_t* a, const uint32_t* b) {
    asm volatile(
        "mma.sync.aligned.m16n8k16.row.col.f32.f16.f16.f32 "
        "{%0,%1,%2,%3}, {%4,%5,%6,%7}, {%8,%9}, {%0,%1,%2,%3};"
        : "+f"(d[0]), "+f"(d[1]), "+f"(d[2]), "+f"(d[3])
        : "r"(a[0]), "r"(a[1]), "r"(a[2]), "r"(a[3]), "r"(b[0]), "r"(b[1]));
}
__device__ __forceinline__ uint32_t packh2(__half lo, __half hi) {
    return ((uint32_t)__half_as_ushort(hi) << 16) | __half_as_ushort(lo);
}
__device__ __forceinline__ void cp_async16(uint32_t dst, const void* src) {
    asm volatile("cp.async.cg.shared.global [%0], [%1], 16;" :: "r"(dst), "l"(src));
}
__device__ __forceinline__ void cp_commit() { asm volatile("cp.async.commit_group;"); }
__device__ __forceinline__ void cp_wait0() { asm volatile("cp.async.wait_group 0;"); }
__device__ __forceinline__ void cp_wait1() { asm volatile("cp.async.wait_group 1;"); }

// ---------------------------------------------------------------------------
// Weight transpose + fp16 convert, 4 weights per launch
// ---------------------------------------------------------------------------
__global__ void wconv4_kernel(const float* __restrict__ W0,
                              const float* __restrict__ W1,
                              const float* __restrict__ W2,
                              const float* __restrict__ W3) {
    __shared__ float t[32][33];
    int z = blockIdx.z;
    const float* W = (z == 0) ? W0 : (z == 1) ? W1 : (z == 2) ? W2 : W3;
    size_t base = (size_t)z * DD * DD;
    int k0 = blockIdx.y * 32, n0 = blockIdx.x * 32;
    t[threadIdx.y][threadIdx.x] = W[(k0 + threadIdx.y) * DD + n0 + threadIdx.x];
    __syncthreads();
    g_wh[base + (size_t)(n0 + threadIdx.y) * DD + k0 + threadIdx.x] =
        __float2half_rn(t[threadIdx.x][threadIdx.y]);
}

// ---------------------------------------------------------------------------
// Activation fp16 convert, 3 inputs per launch
// ---------------------------------------------------------------------------
__global__ void aconv3_kernel(const float4* __restrict__ a0,
                              const float4* __restrict__ a1,
                              const float4* __restrict__ a2) {
    int z = blockIdx.y;
    const float4* in = (z == 0) ? a0 : (z == 1) ? a1 : a2;
    int idx = blockIdx.x * blockDim.x + threadIdx.x;
    float4 a = in[idx];
    ((uint2*)g_ah)[(size_t)z * (GM * GK / 4) + idx] = make_uint2(
        packh2(__float2half_rn(a.x), __float2half_rn(a.y)),
        packh2(__float2half_rn(a.z), __float2half_rn(a.w)));
}

// ---------------------------------------------------------------------------
// RoPE tables
// ---------------------------------------------------------------------------
__global__ void rope_table_kernel() {
    int idx = blockIdx.x * blockDim.x + threadIdx.x;
    int p = idx >> 5, i = idx & 31;
    double inv = exp(-((double)(2 * i) / 64.0) * log(10000.0));
    float angf = (float)((double)p * inv);
    double a = (double)angf;
    double n = rint(a * 0.15915494309189535);
    float r = (float)(a - n * 6.283185307179586);
    g_cos[p * 32 + i] = cosf(r);
    g_sin[p * 32 + i] = sinf(r);
}

// ---------------------------------------------------------------------------
// GEMM fp16: CTA 128x128, warp tile 32x64 (4M x 2N warps), BK=64,
// 2-stage cp.async, 2 CTAs/SM.  B fragments via ldsm_x4 (2 n-tiles per load).
// mode 1: fused epilogue (bias + RoPE for z<2; Q scaled 0.125) -> fp16 [B,H,S,DK]
// mode 0: f32 epilogue with bias -> C   (A slot 0, W slot 3)
// ---------------------------------------------------------------------------
#define ST_B   18432           // 128 rows * 144
#define STAGEH 36864
#define GEMM_SMEM (2 * STAGEH) // 73728

__global__ void __launch_bounds__(256, 2) gemm_f16_kernel(
    int mode,
    const float* __restrict__ bq, const float* __restrict__ bk,
    const float* __restrict__ bv,
    float* __restrict__ C) {
    extern __shared__ char smem[];
    uint32_t sbase = smem_u32(smem);

    int tid = threadIdx.x;
    int lane = tid & 31, w = tid >> 5;
    int wm = w & 3, wn = w >> 2;         // 4 M-warps x 2 N-warps
    int bm = blockIdx.y * 128, bn = blockIdx.x * 128;
    int z = blockIdx.z;
    int aslot = mode ? z : 0;
    int wslot = mode ? z : 3;

    const __half* Ah = g_ah + (size_t)aslot * GM * GK;
    const __half* Bh = g_wh + (size_t)wslot * DD * DD;

    float acc[2][8][4] = {};

    uint32_t a_row  = wm * 32 + (lane & 15);
    uint32_t a_coff = (lane >> 4) * 16;
    // B x4 addressing: lane groups -> (tile, k-half)
    uint32_t b_row4 = wn * 64 + ((lane >> 4) & 1) * 8 + (lane & 7);
    uint32_t b_coff = ((lane >> 3) & 1) * 16;

    auto load_stage = [&](int k0, int stage) {
        uint32_t stb = sbase + stage * STAGEH;
#pragma unroll
        for (int i = 0; i < 8; i++) {
            int idx = tid + i * 256;   // 0..2047
            if (idx < 1024) {          // A: 128 rows x 8 chunks (64 cols)
                int r = idx >> 3, c = idx & 7;
                cp_async16(stb + r * PITCH + c * 16,
                           Ah + (size_t)(bm + r) * GK + k0 + c * 8);
            } else {                   // B: 128 rows x 8 chunks
                int j = idx - 1024;
                int r = j >> 3, c = j & 7;
                cp_async16(stb + ST_B + r * PITCH + c * 16,
                           Bh + (size_t)(bn + r) * GK + k0 + c * 8);
            }
        }
        cp_commit();
    };

    const int NC = GK / 64;
    load_stage(0, 0);
    int buf = 0;

    for (int c = 0; c < NC; c++) {
        cp_wait0();
        __syncthreads();
        if (c + 1 < NC) load_stage((c + 1) * 64, buf ^ 1);

        uint32_t stb = sbase + buf * STAGEH;
#pragma unroll
        for (int ks = 0; ks < 4; ks++) {
            uint32_t kb = ks * 32;     // 16 cols * 2B per k-step
            uint32_t ah[2][4], bh[8][2];
#pragma unroll
            for (int mi = 0; mi < 2; mi++)
                ldsm_x4(ah[mi], stb + (a_row + mi * 16) * PITCH + kb + a_coff);
#pragma unroll
            for (int ni = 0; ni < 8; ni += 2) {
                uint32_t b4[4];
                ldsm_x4(b4, stb + ST_B + (b_row4 + ni * 8) * PITCH + kb + b_coff);
                bh[ni][0] = b4[0];     bh[ni][1] = b4[1];
                bh[ni + 1][0] = b4[2]; bh[ni + 1][1] = b4[3];
            }
#pragma unroll
            for (int mi = 0; mi < 2; mi++)
#pragma unroll
                for (int ni = 0; ni < 8; ni++)
                    mma_f16(acc[mi][ni], ah[mi], bh[ni]);
        }
        buf ^= 1;
    }

    int r0 = bm + wm * 32 + (lane >> 2);
    int c0 = bn + wn * 64 + (lane & 3) * 2;

    if (mode == 0) {
        const float* bias = bq;   // caller passes bo here
#pragma unroll
        for (int mi = 0; mi < 2; mi++) {
#pragma unroll
            for (int ni = 0; ni < 8; ni++) {
                int row = r0 + mi * 16;
                int col = c0 + ni * 8;
                float bb0 = bias[col], bb1 = bias[col + 1];
                *(float2*)&C[(size_t)row * GN + col] =
                    make_float2(acc[mi][ni][0] + bb0, acc[mi][ni][1] + bb1);
                *(float2*)&C[(size_t)(row + 8) * GN + col] =
                    make_float2(acc[mi][ni][2] + bb0, acc[mi][ni][3] + bb1);
            }
        }
        return;
    }

    // fused epilogue: bias + (RoPE for z<2) -> fp16 [B,H,S,DK]
    const float* bias = (z == 0) ? bq : (z == 1) ? bk : bv;
    __half* outh = (z == 0) ? g_qh2 : (z == 1) ? g_kh2 : g_vh2;
    int hh = (bn >> 6) + wn;
    float qscale = (z == 0) ? 0.125f : 1.0f;   // fold softmax scale into Q

    if (z == 2) {
#pragma unroll
        for (int mi = 0; mi < 2; mi++) {
#pragma unroll
            for (int hf = 0; hf < 2; hf++) {
                int row = r0 + mi * 16 + hf * 8;
                int s = row & (SS - 1), bb = row >> 11;
                size_t base = ((size_t)(bb * HH + hh) * SS + s) * 64;
#pragma unroll
                for (int ni = 0; ni < 8; ni++) {
                    int d = (lane & 3) * 2 + ni * 8;
                    int cn = c0 + ni * 8;
                    *(__half2*)&outh[base + d] = __floats2half2_rn(
                        acc[mi][ni][2 * hf]     + bias[cn],
                        acc[mi][ni][2 * hf + 1] + bias[cn + 1]);
                }
            }
        }
    } else {
#pragma unroll
        for (int mi = 0; mi < 2; mi++) {
#pragma unroll
            for (int hf = 0; hf < 2; hf++) {
                int row = r0 + mi * 16 + hf * 8;
                int s = row & (SS - 1), bb = row >> 11;
                size_t base = ((size_t)(bb * HH + hh) * SS + s) * 64;
#pragma unroll
                for (int ni = 0; ni < 4; ni++) {
                    int d = (lane & 3) * 2 + ni * 8;
                    int cn = c0 + ni * 8;
                    float x0a = acc[mi][ni][2 * hf]       + bias[cn];
                    float x0b = acc[mi][ni][2 * hf + 1]   + bias[cn + 1];
                    float x1a = acc[mi][ni + 4][2 * hf]     + bias[cn + 32];
                    float x1b = acc[mi][ni + 4][2 * hf + 1] + bias[cn + 33];
                    float cA = g_cos[s * 32 + d],  cB = g_cos[s * 32 + d + 1];
                    float sA = g_sin[s * 32 + d],  sB = g_sin[s * 32 + d + 1];
                    *(__half2*)&outh[base + d] = __floats2half2_rn(
                        (x0a * cA - x1a * sA) * qscale, (x0b * cB - x1b * sB) * qscale);
                    *(__half2*)&outh[base + d + 32] = __floats2half2_rn(
                        (x1a * cA + x0a * sA) * qscale, (x1b * cB + x0b * sB) * qscale);
                }
            }
        }
    }
}

// ---------------------------------------------------------------------------
// Flash attention, fp16 mma.sync, 3-stage cp.async KV pipeline, 2 CTAs/SM.
// Q pre-scaled by 0.125; K/V fragment loads via ldsm_x4; heavy tiles first.
// ---------------------------------------------------------------------------
#define APITCH 144
#define AS_Q   0
#define AS_KV  18432
#define KVSTG  18432
#define ATTN_SMEM (18432 + 3 * KVSTG)   // 73728

__global__ void __launch_bounds__(256, 2) attn_f16_kernel() {
    extern __shared__ char smem[];
    uint32_t sbase = smem_u32(smem);
    int tid = threadIdx.x;
    int lane = tid & 31, w = tid >> 5;
    int qt = (SS / 128 - 1) - blockIdx.x;   // heavy-first scheduling
    int h = blockIdx.y, b = blockIdx.z;

    size_t hb   = (size_t)(b * HH + h) * SS * DKK;
    size_t qoff = hb + (size_t)qt * 128 * DKK;

    auto load_kv = [&](int j0, int stage) {
        size_t kvb = hb + (size_t)j0 * 64 * DKK;
        uint32_t stb = sbase + AS_KV + stage * KVSTG;
#pragma unroll
        for (int i = 0; i < 4; i++) {
            int idx = tid + i * 256;
            int arr = idx >> 9;
            int s2 = idx & 511;
            int r = s2 >> 3, c = s2 & 7;
            const __half* src = (arr ? g_vh2 : g_kh2) + kvb + r * 64 + c * 8;
            cp_async16(stb + arr * 9216 + r * APITCH + c * 16, src);
        }
        cp_commit();
    };

    {
        const uint4* q4 = (const uint4*)g_qh2 + qoff / 8;
#pragma unroll
        for (int i = 0; i < 4; i++) {
            int idx = tid + i * 256;
            int r = idx >> 3, c = idx & 7;
            *(uint4*)(smem + AS_Q + r * APITCH + c * 16) = q4[r * 8 + c];
        }
    }
    int jmax = 2 * qt + 1;
    load_kv(0, 0);
    load_kv(1, 1);
    __syncthreads();

    uint32_t qf[4][4];
    {
        uint32_t arow = w * 16 + (lane & 15);
        uint32_t acoff = (lane >> 4) * 16;
#pragma unroll
        for (int ks = 0; ks < 4; ks++)
            ldsm_x4(qf[ks], sbase + AS_Q + arow * APITCH + ks * 32 + acoff);
    }

    float o[8][4] = {};
    float m0 = -1e30f, m1 = -1e30f, l0 = 0.0f, l1 = 0.0f;
    int row0 = qt * 128 + w * 16 + (lane >> 2);
    int row1 = row0 + 8;

    // x4 fragment addressing
    uint32_t k_row4 = ((lane >> 4) & 1) * 8 + (lane & 7);
    uint32_t k_coff = ((lane >> 3) & 1) * 16;
    uint32_t v_rowp = (lane & 7) + ((lane >> 3) & 1) * 8;
    uint32_t v_coff = (lane >> 4) * 16;

    for (int j0 = 0; j0 <= jmax; j0++) {
        if (j0 < jmax) cp_wait1(); else cp_wait0();
        __syncthreads();
        if (j0 + 2 <= jmax) load_kv(j0 + 2, (j0 + 2) % 3);

        uint32_t kvb_s = sbase + AS_KV + (j0 % 3) * KVSTG;

        float sacc[8][4] = {};
#pragma unroll
        for (int ks = 0; ks < 4; ks++) {
#pragma unroll
            for (int nt = 0; nt < 8; nt += 2) {
                uint32_t k4[4];
                ldsm_x4(k4, kvb_s + (nt * 8 + k_row4) * APITCH + ks * 32 + k_coff);
                mma_f16(sacc[nt],     qf[ks], k4);
                mma_f16(sacc[nt + 1], qf[ks], k4 + 2);
            }
        }

        bool domask = (j0 >= 2 * qt);
        int colb = j0 * 64 + (lane & 3) * 2;
        float mx0 = -1e30f, mx1 = -1e30f;
#pragma unroll
        for (int nt = 0; nt < 8; nt++) {
            float s0 = sacc[nt][0];
            float s1 = sacc[nt][1];
            float s2 = sacc[nt][2];
            float s3 = sacc[nt][3];
            if (domask) {
                int c0 = colb + nt * 8;
                if (c0     > row0) s0 = -1e30f;
                if (c0 + 1 > row0) s1 = -1e30f;
                if (c0     > row1) s2 = -1e30f;
                if (c0 + 1 > row1) s3 = -1e30f;
            }
            sacc[nt][0] = s0; sacc[nt][1] = s1;
            sacc[nt][2] = s2; sacc[nt][3] = s3;
            mx0 = fmaxf(mx0, fmaxf(s0, s1));
            mx1 = fmaxf(mx1, fmaxf(s2, s3));
        }
        mx0 = fmaxf(mx0, __shfl_xor_sync(0xffffffffu, mx0, 1));
        mx0 = fmaxf(mx0, __shfl_xor_sync(0xffffffffu, mx0, 2));
        mx1 = fmaxf(mx1, __shfl_xor_sync(0xffffffffu, mx1, 1));
        mx1 = fmaxf(mx1, __shfl_xor_sync(0xffffffffu, mx1, 2));

        float mn0 = fmaxf(m0, mx0), mn1 = fmaxf(m1, mx1);
        float al0 = __expf(m0 - mn0), al1 = __expf(m1 - mn1);
        m0 = mn0; m1 = mn1;

        uint32_t pf[8][2];
        float ls0 = 0.0f, ls1 = 0.0f;
#pragma unroll
        for (int nt = 0; nt < 8; nt++) {
            float p0 = __expf(sacc[nt][0] - mn0);
            float p1 = __expf(sacc[nt][1] - mn0);
            float p2 = __expf(sacc[nt][2] - mn1);
            float p3 = __expf(sacc[nt][3] - mn1);
            ls0 += p0 + p1; ls1 += p2 + p3;
            pf[nt][0] = packh2(__float2half_rn(p0), __float2half_rn(p1));
            pf[nt][1] = packh2(__float2half_rn(p2), __float2half_rn(p3));
        }
        l0 = l0 * al0 + ls0;
        l1 = l1 * al1 + ls1;
#pragma unroll
        for (int nt = 0; nt < 8; nt++) {
            o[nt][0] *= al0; o[nt][1] *= al0;
            o[nt][2] *= al1; o[nt][3] *= al1;
        }

#pragma unroll
        for (int ks = 0; ks < 4; ks++) {
            uint32_t pa[4] = {pf[2*ks][0], pf[2*ks][1], pf[2*ks+1][0], pf[2*ks+1][1]};
#pragma unroll
            for (int dn = 0; dn < 8; dn += 2) {
                uint32_t v4[4];
                ldsm_x4_t(v4, kvb_s + 9216
                    + (ks * 16 + v_rowp) * APITCH + dn * 16 + v_coff);
                mma_f16(o[dn],     pa, v4);
                mma_f16(o[dn + 1], pa, v4 + 2);
            }
        }
    }

    float lr0 = l0 + __shfl_xor_sync(0xffffffffu, l0, 1);
    lr0 += __shfl_xor_sync(0xffffffffu, lr0, 2);
    float lr1 = l1 + __shfl_xor_sync(0xffffffffu, l1, 1);
    lr1 += __shfl_xor_sync(0xffffffffu, lr1, 2);
    float inv0 = 1.0f / lr0, inv1 = 1.0f / lr1;

    __half* O0 = g_ah + ((size_t)b * SS + row0) * DD + h * 64;
    __half* O1 = g_ah + ((size_t)b * SS + row1) * DD + h * 64;
#pragma unroll
    for (int dn = 0; dn < 8; dn++) {
        int col = dn * 8 + (lane & 3) * 2;
        *(__half2*)&O0[col] = __floats2half2_rn(o[dn][0] * inv0, o[dn][1] * inv0);
        *(__half2*)&O1[col] = __floats2half2_rn(o[dn][2] * inv1, o[dn][3] * inv1);
    }
}

// ---------------------------------------------------------------------------
// Launch
// ---------------------------------------------------------------------------
extern "C" void kernel_launch(void* const* d_in, const int* in_sizes, int n_in,
                              void* d_out, int out_size) {
    const float* q  = (const float*)d_in[0];
    const float* k  = (const float*)d_in[1];
    const float* v  = (const float*)d_in[2];
    const float* Wq = (const float*)d_in[4];
    const float* bq = (const float*)d_in[5];
    const float* Wk = (const float*)d_in[6];
    const float* bk = (const float*)d_in[7];
    const float* Wv = (const float*)d_in[8];
    const float* bv = (const float*)d_in[9];
    const float* Wo = (const float*)d_in[10];
    const float* bo = (const float*)d_in[11];
    float* out = (float*)d_out;

    cudaFuncSetAttribute(gemm_f16_kernel, cudaFuncAttributeMaxDynamicSharedMemorySize, GEMM_SMEM);
    cudaFuncSetAttribute(attn_f16_kernel, cudaFuncAttributeMaxDynamicSharedMemorySize, ATTN_SMEM);

    const int NCONV = (GM * GK / 4) / 256;   // 4096

    aconv3_kernel<<<dim3(NCONV, 3), 256>>>((const float4*)q, (const float4*)k, (const float4*)v);
    wconv4_kernel<<<dim3(32, 32, 4), dim3(32, 32)>>>(Wq, Wk, Wv, Wo);
    rope_table_kernel<<<256, 256>>>();

    // QKV projection, fused bias+RoPE+fp16 epilogue (Q pre-scaled 0.125)
    gemm_f16_kernel<<<dim3(GN / 128, GM / 128, 3), 256, GEMM_SMEM>>>(
        1, bq, bk, bv, nullptr);

    // attention (writes fp16 to g_ah slot 0)
    attn_f16_kernel<<<dim3(SS / 128, HH, BB), 256, ATTN_SMEM>>>();

    // output projection
    gemm_f16_kernel<<<dim3(GN / 128, GM / 128, 1), 256, GEMM_SMEM>>>(
        0, bo, nullptr, nullptr, out);
}

// round 14
// speedup vs baseline: 1.5046x; 1.5046x over previous
#include <cuda_runtime.h>
#include <cuda_fp16.h>
#include <cstdint>
#include <math.h>

#define BB 2
#define SS 2048
#define DD 1024
#define HH 16
#define DKK 64

#define GM 4096
#define GN 1024
#define GK 1024
#define PITCH 144   // gemm smem row pitch: 64 fp16 + 8 pad

// ---------------------------------------------------------------------------
// Scratch
// ---------------------------------------------------------------------------
__device__ float g_cos[SS*32];
__device__ float g_sin[SS*32];
__device__ __half g_wh[4*DD*DD];   // fp16 weights [N,K]: Wq,Wk,Wv,Wo
__device__ __half g_ah[3*GM*GK];   // fp16 activations; slot0 reused for attn out
__device__ __half g_qh2[BB*SS*DD]; // [B,H,S,DK] (pre-scaled by 0.125)
__device__ __half g_kh2[BB*SS*DD];
__device__ __half g_vh2[BB*SS*DD];

// ---------------------------------------------------------------------------
// helpers
// ---------------------------------------------------------------------------
__device__ __forceinline__ uint32_t smem_u32(const void* p) {
    uint32_t a;
    asm("{ .reg .u64 t; cvta.to.shared.u64 t, %1; cvt.u32.u64 %0, t; }"
        : "=r"(a) : "l"(p));
    return a;
}
__device__ __forceinline__ void ldsm_x4(uint32_t* r, uint32_t addr) {
    asm volatile("ldmatrix.sync.aligned.m8n8.x4.shared.b16 {%0,%1,%2,%3}, [%4];"
        : "=r"(r[0]), "=r"(r[1]), "=r"(r[2]), "=r"(r[3]) : "r"(addr));
}
__device__ __forceinline__ void ldsm_x4_t(uint32_t* r, uint32_t addr) {
    asm volatile("ldmatrix.sync.aligned.m8n8.x4.trans.shared.b16 {%0,%1,%2,%3}, [%4];"
        : "=r"(r[0]), "=r"(r[1]), "=r"(r[2]), "=r"(r[3]) : "r"(addr));
}
__device__ __forceinline__ void mma_f16(float* d, const uint32_t* a, const uint32_t* b) {
    asm volatile(
        "mma.sync.aligned.m16n8k16.row.col.f32.f16.f16.f32 "
        "{%0,%1,%2,%3}, {%4,%5,%6,%7}, {%8,%9}, {%0,%1,%2,%3};"
        : "+f"(d[0]), "+f"(d[1]), "+f"(d[2]), "+f"(d[3])
        : "r"(a[0]), "r"(a[1]), "r"(a[2]), "r"(a[3]), "r"(b[0]), "r"(b[1]));
}
__device__ __forceinline__ uint32_t packh2(__half lo, __half hi) {
    return ((uint32_t)__half_as_ushort(hi) << 16) | __half_as_ushort(lo);
}
__device__ __forceinline__ void cp_async16(uint32_t dst, const void* src) {
    asm volatile("cp.async.cg.shared.global [%0], [%1], 16;" :: "r"(dst), "l"(src));
}
__device__ __forceinline__ void cp_commit() { asm volatile("cp.async.commit_group;"); }
__device__ __forceinline__ void cp_wait0() { asm volatile("cp.async.wait_group 0;"); }
__device__ __forceinline__ void cp_wait1() { asm volatile("cp.async.wait_group 1;"); }

// ---------------------------------------------------------------------------
// Weight transpose + fp16 convert, 4 weights per launch
// ---------------------------------------------------------------------------
__global__ void wconv4_kernel(const float* __restrict__ W0,
                              const float* __restrict__ W1,
                              const float* __restrict__ W2,
                              const float* __restrict__ W3) {
    __shared__ float t[32][33];
    int z = blockIdx.z;
    const float* W = (z == 0) ? W0 : (z == 1) ? W1 : (z == 2) ? W2 : W3;
    size_t base = (size_t)z * DD * DD;
    int k0 = blockIdx.y * 32, n0 = blockIdx.x * 32;
    t[threadIdx.y][threadIdx.x] = W[(k0 + threadIdx.y) * DD + n0 + threadIdx.x];
    __syncthreads();
    g_wh[base + (size_t)(n0 + threadIdx.y) * DD + k0 + threadIdx.x] =
        __float2half_rn(t[threadIdx.x][threadIdx.y]);
}

// ---------------------------------------------------------------------------
// Activation fp16 convert, 3 inputs per launch
// ---------------------------------------------------------------------------
__global__ void aconv3_kernel(const float4* __restrict__ a0,
                              const float4* __restrict__ a1,
                              const float4* __restrict__ a2) {
    int z = blockIdx.y;
    const float4* in = (z == 0) ? a0 : (z == 1) ? a1 : a2;
    int idx = blockIdx.x * blockDim.x + threadIdx.x;
    float4 a = in[idx];
    ((uint2*)g_ah)[(size_t)z * (GM * GK / 4) + idx] = make_uint2(
        packh2(__float2half_rn(a.x), __float2half_rn(a.y)),
        packh2(__float2half_rn(a.z), __float2half_rn(a.w)));
}

// ---------------------------------------------------------------------------
// RoPE tables
// ---------------------------------------------------------------------------
__global__ void rope_table_kernel() {
    int idx = blockIdx.x * blockDim.x + threadIdx.x;
    int p = idx >> 5, i = idx & 31;
    double inv = exp(-((double)(2 * i) / 64.0) * log(10000.0));
    float angf = (float)((double)p * inv);
    double a = (double)angf;
    double n = rint(a * 0.15915494309189535);
    float r = (float)(a - n * 6.283185307179586);
    g_cos[p * 32 + i] = cosf(r);
    g_sin[p * 32 + i] = sinf(r);
}

// ---------------------------------------------------------------------------
// GEMM fp16: CTA 128x128, warp tile 32x64 (4M x 2N warps), BK=64,
// 2-stage cp.async, 2 CTAs/SM.  B fragments via ldsm_x4 (2 n-tiles per load).
// mode 1: fused epilogue (bias + RoPE for z<2; Q scaled 0.125) -> fp16 [B,H,S,DK]
// mode 0: f32 epilogue with bias -> C   (A slot 0, W slot 3)
// ---------------------------------------------------------------------------
#define ST_B   18432           // 128 rows * 144
#define STAGEH 36864
#define GEMM_SMEM (2 * STAGEH) // 73728

__global__ void __launch_bounds__(256, 2) gemm_f16_kernel(
    int mode,
    const float* __restrict__ bq, const float* __restrict__ bk,
    const float* __restrict__ bv,
    float* __restrict__ C) {
    extern __shared__ char smem[];
    uint32_t sbase = smem_u32(smem);

    int tid = threadIdx.x;
    int lane = tid & 31, w = tid >> 5;
    int wm = w & 3, wn = w >> 2;         // 4 M-warps x 2 N-warps
    int bm = blockIdx.y * 128, bn = blockIdx.x * 128;
    int z = blockIdx.z;
    int aslot = mode ? z : 0;
    int wslot = mode ? z : 3;

    const __half* Ah = g_ah + (size_t)aslot * GM * GK;
    const __half* Bh = g_wh + (size_t)wslot * DD * DD;

    float acc[2][8][4] = {};

    uint32_t a_row  = wm * 32 + (lane & 15);
    uint32_t a_coff = (lane >> 4) * 16;
    // B x4 addressing: lane groups -> (tile, k-half)
    uint32_t b_row4 = wn * 64 + ((lane >> 4) & 1) * 8 + (lane & 7);
    uint32_t b_coff = ((lane >> 3) & 1) * 16;

    auto load_stage = [&](int k0, int stage) {
        uint32_t stb = sbase + stage * STAGEH;
#pragma unroll
        for (int i = 0; i < 8; i++) {
            int idx = tid + i * 256;   // 0..2047
            if (idx < 1024) {          // A: 128 rows x 8 chunks (64 cols)
                int r = idx >> 3, c = idx & 7;
                cp_async16(stb + r * PITCH + c * 16,
                           Ah + (size_t)(bm + r) * GK + k0 + c * 8);
            } else {                   // B: 128 rows x 8 chunks
                int j = idx - 1024;
                int r = j >> 3, c = j & 7;
                cp_async16(stb + ST_B + r * PITCH + c * 16,
                           Bh + (size_t)(bn + r) * GK + k0 + c * 8);
            }
        }
        cp_commit();
    };

    const int NC = GK / 64;
    load_stage(0, 0);
    int buf = 0;

    for (int c = 0; c < NC; c++) {
        cp_wait0();
        __syncthreads();
        if (c + 1 < NC) load_stage((c + 1) * 64, buf ^ 1);

        uint32_t stb = sbase + buf * STAGEH;
#pragma unroll
        for (int ks = 0; ks < 4; ks++) {
            uint32_t kb = ks * 32;     // 16 cols * 2B per k-step
            uint32_t ah[2][4], bh[8][2];
#pragma unroll
            for (int mi = 0; mi < 2; mi++)
                ldsm_x4(ah[mi], stb + (a_row + mi * 16) * PITCH + kb + a_coff);
#pragma unroll
            for (int ni = 0; ni < 8; ni += 2) {
                uint32_t b4[4];
                ldsm_x4(b4, stb + ST_B + (b_row4 + ni * 8) * PITCH + kb + b_coff);
                bh[ni][0] = b4[0];     bh[ni][1] = b4[1];
                bh[ni + 1][0] = b4[2]; bh[ni + 1][1] = b4[3];
            }
#pragma unroll
            for (int mi = 0; mi < 2; mi++)
#pragma unroll
                for (int ni = 0; ni < 8; ni++)
                    mma_f16(acc[mi][ni], ah[mi], bh[ni]);
        }
        buf ^= 1;
    }

    int r0 = bm + wm * 32 + (lane >> 2);
    int c0 = bn + wn * 64 + (lane & 3) * 2;

    if (mode == 0) {
        const float* bias = bq;   // caller passes bo here
#pragma unroll
        for (int mi = 0; mi < 2; mi++) {
#pragma unroll
            for (int ni = 0; ni < 8; ni++) {
                int row = r0 + mi * 16;
                int col = c0 + ni * 8;
                float bb0 = bias[col], bb1 = bias[col + 1];
                *(float2*)&C[(size_t)row * GN + col] =
                    make_float2(acc[mi][ni][0] + bb0, acc[mi][ni][1] + bb1);
                *(float2*)&C[(size_t)(row + 8) * GN + col] =
                    make_float2(acc[mi][ni][2] + bb0, acc[mi][ni][3] + bb1);
            }
        }
        return;
    }

    // fused epilogue: bias + (RoPE for z<2) -> fp16 [B,H,S,DK]
    const float* bias = (z == 0) ? bq : (z == 1) ? bk : bv;
    __half* outh = (z == 0) ? g_qh2 : (z == 1) ? g_kh2 : g_vh2;
    int hh = (bn >> 6) + wn;
    float qscale = (z == 0) ? 0.125f : 1.0f;   // fold softmax scale into Q

    if (z == 2) {
#pragma unroll
        for (int mi = 0; mi < 2; mi++) {
#pragma unroll
            for (int hf = 0; hf < 2; hf++) {
                int row = r0 + mi * 16 + hf * 8;
                int s = row & (SS - 1), bb = row >> 11;
                size_t base = ((size_t)(bb * HH + hh) * SS + s) * 64;
#pragma unroll
                for (int ni = 0; ni < 8; ni++) {
                    int d = (lane & 3) * 2 + ni * 8;
                    int cn = c0 + ni * 8;
                    *(__half2*)&outh[base + d] = __floats2half2_rn(
                        acc[mi][ni][2 * hf]     + bias[cn],
                        acc[mi][ni][2 * hf + 1] + bias[cn + 1]);
                }
            }
        }
    } else {
#pragma unroll
        for (int mi = 0; mi < 2; mi++) {
#pragma unroll
            for (int hf = 0; hf < 2; hf++) {
                int row = r0 + mi * 16 + hf * 8;
                int s = row & (SS - 1), bb = row >> 11;
                size_t base = ((size_t)(bb * HH + hh) * SS + s) * 64;
#pragma unroll
                for (int ni = 0; ni < 4; ni++) {
                    int d = (lane & 3) * 2 + ni * 8;
                    int cn = c0 + ni * 8;
                    float x0a = acc[mi][ni][2 * hf]       + bias[cn];
                    float x0b = acc[mi][ni][2 * hf + 1]   + bias[cn + 1];
                    float x1a = acc[mi][ni + 4][2 * hf]     + bias[cn + 32];
                    float x1b = acc[mi][ni + 4][2 * hf + 1] + bias[cn + 33];
                    float cA = g_cos[s * 32 + d],  cB = g_cos[s * 32 + d + 1];
                    float sA = g_sin[s * 32 + d],  sB = g_sin[s * 32 + d + 1];
                    *(__half2*)&outh[base + d] = __floats2half2_rn(
                        (x0a * cA - x1a * sA) * qscale, (x0b * cB - x1b * sB) * qscale);
                    *(__half2*)&outh[base + d + 32] = __floats2half2_rn(
                        (x1a * cA + x0a * sA) * qscale, (x1b * cB + x0b * sB) * qscale);
                }
            }
        }
    }
}

// ---------------------------------------------------------------------------
// Flash attention, fp16 mma.sync, 3-stage cp.async KV pipeline, 2 CTAs/SM.
// Q pre-scaled by 0.125; K/V fragment loads via ldsm_x4; heavy tiles first.
// ---------------------------------------------------------------------------
#define APITCH 144
#define AS_Q   0
#define AS_KV  18432
#define KVSTG  18432
#define ATTN_SMEM (18432 + 3 * KVSTG)   // 73728

__global__ void __launch_bounds__(256, 2) attn_f16_kernel() {
    extern __shared__ char smem[];
    uint32_t sbase = smem_u32(smem);
    int tid = threadIdx.x;
    int lane = tid & 31, w = tid >> 5;
    int qt = (SS / 128 - 1) - blockIdx.x;   // heavy-first scheduling
    int h = blockIdx.y, b = blockIdx.z;

    size_t hb   = (size_t)(b * HH + h) * SS * DKK;
    size_t qoff = hb + (size_t)qt * 128 * DKK;

    auto load_kv = [&](int j0, int stage) {
        size_t kvb = hb + (size_t)j0 * 64 * DKK;
        uint32_t stb = sbase + AS_KV + stage * KVSTG;
#pragma unroll
        for (int i = 0; i < 4; i++) {
            int idx = tid + i * 256;
            int arr = idx >> 9;
            int s2 = idx & 511;
            int r = s2 >> 3, c = s2 & 7;
            const __half* src = (arr ? g_vh2 : g_kh2) + kvb + r * 64 + c * 8;
            cp_async16(stb + arr * 9216 + r * APITCH + c * 16, src);
        }
        cp_commit();
    };

    {
        const uint4* q4 = (const uint4*)g_qh2 + qoff / 8;
#pragma unroll
        for (int i = 0; i < 4; i++) {
            int idx = tid + i * 256;
            int r = idx >> 3, c = idx & 7;
            *(uint4*)(smem + AS_Q + r * APITCH + c * 16) = q4[r * 8 + c];
        }
    }
    int jmax = 2 * qt + 1;
    load_kv(0, 0);
    load_kv(1, 1);
    __syncthreads();

    uint32_t qf[4][4];
    {
        uint32_t arow = w * 16 + (lane & 15);
        uint32_t acoff = (lane >> 4) * 16;
#pragma unroll
        for (int ks = 0; ks < 4; ks++)
            ldsm_x4(qf[ks], sbase + AS_Q + arow * APITCH + ks * 32 + acoff);
    }

    float o[8][4] = {};
    float m0 = -1e30f, m1 = -1e30f, l0 = 0.0f, l1 = 0.0f;
    int row0 = qt * 128 + w * 16 + (lane >> 2);
    int row1 = row0 + 8;

    // x4 fragment addressing
    uint32_t k_row4 = ((lane >> 4) & 1) * 8 + (lane & 7);
    uint32_t k_coff = ((lane >> 3) & 1) * 16;
    uint32_t v_rowp = (lane & 7) + ((lane >> 3) & 1) * 8;
    uint32_t v_coff = (lane >> 4) * 16;

    for (int j0 = 0; j0 <= jmax; j0++) {
        if (j0 < jmax) cp_wait1(); else cp_wait0();
        __syncthreads();
        if (j0 + 2 <= jmax) load_kv(j0 + 2, (j0 + 2) % 3);

        uint32_t kvb_s = sbase + AS_KV + (j0 % 3) * KVSTG;

        float sacc[8][4] = {};
#pragma unroll
        for (int ks = 0; ks < 4; ks++) {
#pragma unroll
            for (int nt = 0; nt < 8; nt += 2) {
                uint32_t k4[4];
                ldsm_x4(k4, kvb_s + (nt * 8 + k_row4) * APITCH + ks * 32 + k_coff);
                mma_f16(sacc[nt],     qf[ks], k4);
                mma_f16(sacc[nt + 1], qf[ks], k4 + 2);
            }
        }

        bool domask = (j0 >= 2 * qt);
        int colb = j0 * 64 + (lane & 3) * 2;
        float mx0 = -1e30f, mx1 = -1e30f;
#pragma unroll
        for (int nt = 0; nt < 8; nt++) {
            float s0 = sacc[nt][0];
            float s1 = sacc[nt][1];
            float s2 = sacc[nt][2];
            float s3 = sacc[nt][3];
            if (domask) {
                int c0 = colb + nt * 8;
                if (c0     > row0) s0 = -1e30f;
                if (c0 + 1 > row0) s1 = -1e30f;
                if (c0     > row1) s2 = -1e30f;
                if (c0 + 1 > row1) s3 = -1e30f;
            }
            sacc[nt][0] = s0; sacc[nt][1] = s1;
            sacc[nt][2] = s2; sacc[nt][3] = s3;
            mx0 = fmaxf(mx0, fmaxf(s0, s1));
            mx1 = fmaxf(mx1, fmaxf(s2, s3));
        }
        mx0 = fmaxf(mx0, __shfl_xor_sync(0xffffffffu, mx0, 1));
        mx0 = fmaxf(mx0, __shfl_xor_sync(0xffffffffu, mx0, 2));
        mx1 = fmaxf(mx1, __shfl_xor_sync(0xffffffffu, mx1, 1));
        mx1 = fmaxf(mx1, __shfl_xor_sync(0xffffffffu, mx1, 2));

        float mn0 = fmaxf(m0, mx0), mn1 = fmaxf(m1, mx1);
        float al0 = __expf(m0 - mn0), al1 = __expf(m1 - mn1);
        m0 = mn0; m1 = mn1;

        uint32_t pf[8][2];
        float ls0 = 0.0f, ls1 = 0.0f;
#pragma unroll
        for (int nt = 0; nt < 8; nt++) {
            float p0 = __expf(sacc[nt][0] - mn0);
            float p1 = __expf(sacc[nt][1] - mn0);
            float p2 = __expf(sacc[nt][2] - mn1);
            float p3 = __expf(sacc[nt][3] - mn1);
            ls0 += p0 + p1; ls1 += p2 + p3;
            pf[nt][0] = packh2(__float2half_rn(p0), __float2half_rn(p1));
            pf[nt][1] = packh2(__float2half_rn(p2), __float2half_rn(p3));
        }
        l0 = l0 * al0 + ls0;
        l1 = l1 * al1 + ls1;
#pragma unroll
        for (int nt = 0; nt < 8; nt++) {
            o[nt][0] *= al0; o[nt][1] *= al0;
            o[nt][2] *= al1; o[nt][3] *= al1;
        }

#pragma unroll
        for (int ks = 0; ks < 4; ks++) {
            uint32_t pa[4] = {pf[2*ks][0], pf[2*ks][1], pf[2*ks+1][0], pf[2*ks+1][1]};
#pragma unroll
            for (int dn = 0; dn < 8; dn += 2) {
                uint32_t v4[4];
                ldsm_x4_t(v4, kvb_s + 9216
                    + (ks * 16 + v_rowp) * APITCH + dn * 16 + v_coff);
                mma_f16(o[dn],     pa, v4);
                mma_f16(o[dn + 1], pa, v4 + 2);
            }
        }
    }

    float lr0 = l0 + __shfl_xor_sync(0xffffffffu, l0, 1);
    lr0 += __shfl_xor_sync(0xffffffffu, lr0, 2);
    float lr1 = l1 + __shfl_xor_sync(0xffffffffu, l1, 1);
    lr1 += __shfl_xor_sync(0xffffffffu, lr1, 2);
    float inv0 = 1.0f / lr0, inv1 = 1.0f / lr1;

    __half* O0 = g_ah + ((size_t)b * SS + row0) * DD + h * 64;
    __half* O1 = g_ah + ((size_t)b * SS + row1) * DD + h * 64;
#pragma unroll
    for (int dn = 0; dn < 8; dn++) {
        int col = dn * 8 + (lane & 3) * 2;
        *(__half2*)&O0[col] = __floats2half2_rn(o[dn][0] * inv0, o[dn][1] * inv0);
        *(__half2*)&O1[col] = __floats2half2_rn(o[dn][2] * inv1, o[dn][3] * inv1);
    }
}

// ---------------------------------------------------------------------------
// Launch
// ---------------------------------------------------------------------------
extern "C" void kernel_launch(void* const* d_in, const int* in_sizes, int n_in,
                              void* d_out, int out_size) {
    const float* q  = (const float*)d_in[0];
    const float* k  = (const float*)d_in[1];
    const float* v  = (const float*)d_in[2];
    const float* Wq = (const float*)d_in[4];
    const float* bq = (const float*)d_in[5];
    const float* Wk = (const float*)d_in[6];
    const float* bk = (const float*)d_in[7];
    const float* Wv = (const float*)d_in[8];
    const float* bv = (const float*)d_in[9];
    const float* Wo = (const float*)d_in[10];
    const float* bo = (const float*)d_in[11];
    float* out = (float*)d_out;

    cudaFuncSetAttribute(gemm_f16_kernel, cudaFuncAttributeMaxDynamicSharedMemorySize, GEMM_SMEM);
    cudaFuncSetAttribute(attn_f16_kernel, cudaFuncAttributeMaxDynamicSharedMemorySize, ATTN_SMEM);

    const int NCONV = (GM * GK / 4) / 256;   // 4096

    aconv3_kernel<<<dim3(NCONV, 3), 256>>>((const float4*)q, (const float4*)k, (const float4*)v);
    wconv4_kernel<<<dim3(32, 32, 4), dim3(32, 32)>>>(Wq, Wk, Wv, Wo);
    rope_table_kernel<<<256, 256>>>();

    // QKV projection, fused bias+RoPE+fp16 epilogue (Q pre-scaled 0.125)
    gemm_f16_kernel<<<dim3(GN / 128, GM / 128, 3), 256, GEMM_SMEM>>>(
        1, bq, bk, bv, nullptr);

    // attention (writes fp16 to g_ah slot 0)
    attn_f16_kernel<<<dim3(SS / 128, HH, BB), 256, ATTN_SMEM>>>();

    // output projection
    gemm_f16_kernel<<<dim3(GN / 128, GM / 128, 1), 256, GEMM_SMEM>>>(
        0, bo, nullptr, nullptr, out);
}